// round 1
// baseline (speedup 1.0000x reference)
#include <cuda_runtime.h>

// Scratch (device globals — no allocation allowed)
#define MAXN 131072
#define HID 128
__device__ int   g_deg[MAXN];
__device__ float g_dinv[MAXN];
__device__ float g_dx[MAXN];
__device__ float g_ssum[MAXN];
__device__ float g_gsum[MAXN];
__device__ float g_v[HID];

__global__ void k_zero(int n) {
    int i = blockIdx.x * blockDim.x + threadIdx.x;
    if (i < n) {
        g_deg[i]  = 0;
        g_ssum[i] = 0.0f;
        g_gsum[i] = 0.0f;
    }
    if (i < HID) g_v[i] = 0.0f;
}

// Pass 1: in-degree histogram over destinations (self loop added later as +1)
__global__ void k_deg(const int* __restrict__ col, int E) {
    int i = blockIdx.x * blockDim.x + threadIdx.x;
    if (i < E) atomicAdd(&g_deg[col[i]], 1);
}

// Pass 2: dinv = rsqrt(deg+1), dx = dinv * x
__global__ void k_dinv(const float* __restrict__ x, int n) {
    int i = blockIdx.x * blockDim.x + threadIdx.x;
    if (i < n) {
        float di = rsqrtf((float)(g_deg[i] + 1));
        g_dinv[i] = di;
        g_dx[i]   = di * x[i];
    }
}

// Pass 3: edge scatter.
//   ssum[c] += dinv[r]*x[r]   (dinv[c] factor applied later)
//   gsum[r] += dinv[c]        (dinv[r] factor applied later)
__global__ void k_scatter(const int* __restrict__ row,
                          const int* __restrict__ col, int E) {
    int i = blockIdx.x * blockDim.x + threadIdx.x;
    if (i < E) {
        int r = row[i];
        int c = col[i];
        atomicAdd(&g_ssum[c], g_dx[r]);
        atomicAdd(&g_gsum[r], g_dinv[c]);
    }
}

// Pass 4: v[f] = sum_r g[r] * relu(W1[f]*s[r] + b1[f])
//   s[r] = dinv[r]*(ssum[r] + dinv[r]*x[r])   (self-loop folded in)
//   g[r] = dinv[r]*(gsum[r] + dinv[r])        (self-loop folded in)
__global__ void __launch_bounds__(HID) k_vred(const float* __restrict__ x,
                                              const float* __restrict__ W1,
                                              const float* __restrict__ b1,
                                              int n) {
    __shared__ float sh_s[HID];
    __shared__ float sh_g[HID];
    int f = threadIdx.x;              // 0..127, one output feature per thread
    float w  = W1[f];
    float bb = b1[f];
    float acc = 0.0f;

    for (int base = blockIdx.x * HID; base < n; base += gridDim.x * HID) {
        int r = base + f;
        float sv = 0.0f, gv = 0.0f;
        if (r < n) {
            float di = g_dinv[r];
            sv = di * (g_ssum[r] + di * x[r]);
            gv = di * (g_gsum[r] + di);
        }
        __syncthreads();
        sh_s[f] = sv;
        sh_g[f] = gv;
        __syncthreads();
        int m = n - base; if (m > HID) m = HID;
        #pragma unroll 8
        for (int j = 0; j < m; j++) {
            acc += sh_g[j] * fmaxf(fmaf(w, sh_s[j], bb), 0.0f);
        }
    }
    atomicAdd(&g_v[f], acc);
}

// Pass 5: out[o] = b2[o] + (1/N) * sum_f v[f] * W2[f, o]
__global__ void k_out(const float* __restrict__ W2,
                      const float* __restrict__ b2,
                      float* __restrict__ out,
                      int out_dim, float inv_n) {
    int o = blockIdx.x * blockDim.x + threadIdx.x;
    if (o >= out_dim) return;
    float acc = 0.0f;
    #pragma unroll 8
    for (int f = 0; f < HID; f++) {
        acc += g_v[f] * W2[f * out_dim + o];
    }
    out[o] = b2[o] + acc * inv_n;
}

extern "C" void kernel_launch(void* const* d_in, const int* in_sizes, int n_in,
                              void* d_out, int out_size) {
    const float* x    = (const float*)d_in[0];        // [N,1]
    const int*   ei   = (const int*)  d_in[1];        // [2,E]
    const float* W1   = (const float*)d_in[2];        // [1,128]
    const float* b1   = (const float*)d_in[3];        // [128]
    const float* W2   = (const float*)d_in[4];        // [128,400]
    const float* b2   = (const float*)d_in[5];        // [400]
    float*       out  = (float*)d_out;                // [400]

    int N = in_sizes[0];            // 100000 (x is N*1 elements)
    int E = in_sizes[1] / 2;        // 1.6M
    const int* row = ei;
    const int* col = ei + E;

    int tb = 256;
    k_zero<<<(N + tb - 1) / tb, tb>>>(N);
    k_deg<<<(E + tb - 1) / tb, tb>>>(col, E);
    k_dinv<<<(N + tb - 1) / tb, tb>>>(x, N);
    k_scatter<<<(E + tb - 1) / tb, tb>>>(row, col, E);
    k_vred<<<296, HID>>>(x, W1, b1, N);               // 2 CTAs/SM worth of blocks
    k_out<<<(out_size + 127) / 128, 128>>>(W2, b2, out, out_size, 1.0f / (float)N);
}